// round 11
// baseline (speedup 1.0000x reference)
#include <cuda_runtime.h>
#include <cuda_bf16.h>
#include <cstdint>

#define NTHREADS 256

// ---- smem: weights only (bf16-element offsets) ----
#define XSTR  136                      // W2 row stride: 272B -> 16B-phase conflict-free ldmatrix
#define ASTR  72                       // Wf row stride: 144B
#define O_W2H 0
#define O_W2L (32 * XSTR)
#define O_WFH (2 * 32 * XSTR)
#define O_WFL (O_WFH + 128 * ASTR)
#define SM_ELEMS (O_WFL + 128 * ASTR)
#define O_BIAS (SM_ELEMS * 2)          // bytes: b2[32]f32 then bf[128]f32
#define O_SCR  (O_BIAS + 4 * (32 + 128))
#define SM_BYTES (O_SCR + 8 * 64 * 4)  // + per-warp o1 scratch (slow path)

typedef unsigned u32;

static __device__ __forceinline__ u32 s2u(const void* p) {
    u32 a;
    asm("{ .reg .u64 t; cvta.to.shared.u64 t, %1; cvt.u32.u64 %0, t; }" : "=r"(a) : "l"(p));
    return a;
}
static __device__ __forceinline__ void bfsplit(float v, __nv_bfloat16& h, __nv_bfloat16& l) {
    h = __float2bfloat16(v);
    l = __float2bfloat16(v - __bfloat162float(h));
}
// (a,b) -> packed bf16x2 hi (RN) + packed bf16x2 lo (residual); 6 instrs
static __device__ __forceinline__ void packhl(float a, float b, u32& h, u32& l) {
    asm("cvt.rn.bf16x2.f32 %0, %1, %2;" : "=r"(h) : "f"(b), "f"(a));
    float ra = a - __uint_as_float(h << 16);
    float rb = b - __uint_as_float(h & 0xffff0000u);
    asm("cvt.rn.bf16x2.f32 %0, %1, %2;" : "=r"(l) : "f"(rb), "f"(ra));
}
static __device__ __forceinline__ void ldmx4(u32 a[4], u32 addr) {
    asm volatile("ldmatrix.sync.aligned.m8n8.x4.shared.b16 {%0,%1,%2,%3}, [%4];"
                 : "=r"(a[0]), "=r"(a[1]), "=r"(a[2]), "=r"(a[3]) : "r"(addr));
}
static __device__ __forceinline__ void mmabf(float c[4], const u32 a[4], u32 b0, u32 b1) {
    asm volatile("mma.sync.aligned.m16n8k16.row.col.f32.bf16.bf16.f32 "
                 "{%0,%1,%2,%3}, {%4,%5,%6,%7}, {%8,%9}, {%0,%1,%2,%3};"
                 : "+f"(c[0]), "+f"(c[1]), "+f"(c[2]), "+f"(c[3])
                 : "r"(a[0]), "r"(a[1]), "r"(a[2]), "r"(a[3]), "r"(b0), "r"(b1));
}

__global__ void __launch_bounds__(NTHREADS, 1)
dynlayer_mma(const float* __restrict__ X,  const float* __restrict__ W1,
             const float* __restrict__ b1, const float* __restrict__ W2,
             const float* __restrict__ b2, const float* __restrict__ Wf,
             const float* __restrict__ bf, float* __restrict__ out, int nrows)
{
    extern __shared__ char smraw[];
    __nv_bfloat16* sh = (__nv_bfloat16*)smraw;
    float* b2s = (float*)(smraw + O_BIAS);
    float* bfs = b2s + 32;
    float* scr = (float*)(smraw + O_SCR);
    const u32 sb = s2u(smraw);
    const int tid = threadIdx.x, wid = tid >> 5, lane = tid & 31;

    // ---- stage weights (bf16 hi/lo, padded row-major) + biases ----
    for (int i = tid; i < 32 * 128; i += NTHREADS) {
        int u = i >> 7, k = i & 127; __nv_bfloat16 h, l; bfsplit(W2[i], h, l);
        sh[O_W2H + u * XSTR + k] = h; sh[O_W2L + u * XSTR + k] = l;
    }
    for (int i = tid; i < 128 * 64; i += NTHREADS) {
        int n = i >> 6, k = i & 63; __nv_bfloat16 h, l; bfsplit(Wf[i], h, l);
        sh[O_WFH + n * ASTR + k] = h; sh[O_WFL + n * ASTR + k] = l;
    }
    if (tid < 32)  b2s[tid] = b2[tid];
    if (tid < 128) bfs[tid] = bf[tid];
    __syncthreads();

    const int q  = lane >> 2;          // row-in-group 0..7
    const int c2 = (lane & 3) * 2;     // k/col pair base

    // ldmatrix B lane-address components
    const int brow  = ((lane >> 4) & 1) * 8 + (lane & 7);
    const int bcolh = ((lane >> 3) & 1) * 8;
    const u32 w2h = sb + (u32)((O_W2H + brow * XSTR + bcolh) * 2);
    const u32 w2l = sb + (u32)((O_W2L + brow * XSTR + bcolh) * 2);
    const u32 wfh = sb + (u32)((O_WFH + brow * ASTR + bcolh) * 2);
    const u32 wfl = sb + (u32)((O_WFL + brow * ASTR + bcolh) * 2);

    float2 b2c[4];
    #pragma unroll
    for (int nb = 0; nb < 4; nb++)
        b2c[nb] = *reinterpret_cast<const float2*>(b2s + nb * 8 + c2);

    const int ntiles = nrows >> 8;     // 256 rows per CTA-tile (32 per warp)
    for (int t = blockIdx.x; t < ntiles; t += gridDim.x) {
        const long rw = ((long)t << 8) + wid * 32;

        // L2 prefetch of next tile's slab (this warp's 32 rows = 16KB)
        if (t + gridDim.x < ntiles) {
            const char* p = (const char*)(X + (rw + (long)gridDim.x * 256) * 128) + lane * 256;
            asm volatile("prefetch.global.L2 [%0];" :: "l"(p));
            asm volatile("prefetch.global.L2 [%0];" :: "l"(p + 8192));
        }

        float s[4] = {0.f, 0.f, 0.f, 0.f};
        float accA[2][4][4], accB[2][4][4];
        #pragma unroll
        for (int blk = 0; blk < 2; blk++)
            #pragma unroll
            for (int nb = 0; nb < 4; nb++)
                #pragma unroll
                for (int j = 0; j < 4; j++) { accA[blk][nb][j] = 0.f; accB[blk][nb][j] = 0.f; }

        // ---- GEMM1: o2 = x @ W2^T (M=32,N=32,K=128); B frags shared by 2 row-blocks ----
        #pragma unroll
        for (int half = 0; half < 2; half++) {
            u32 bh[4][2][4], bl[4][2][4];           // this K-half's W2 fragments
            #pragma unroll
            for (int kb = 0; kb < 4; kb++)
                #pragma unroll
                for (int nbp = 0; nbp < 2; nbp++) {
                    const u32 off = (u32)((nbp * 16 * XSTR + (half * 4 + kb) * 16) * 2);
                    ldmx4(bh[kb][nbp], w2h + off);
                    ldmx4(bl[kb][nbp], w2l + off);
                }
            #pragma unroll
            for (int blk = 0; blk < 2; blk++) {
                const float* xr0 = X + (rw + blk * 16 + q) * 128;
                const float* xr1 = xr0 + 8 * 128;
                float2 xf[4][4];
                #pragma unroll
                for (int kb = 0; kb < 4; kb++) {
                    const int col0 = (half * 4 + kb) * 16 + c2;
                    xf[kb][0] = *reinterpret_cast<const float2*>(xr0 + col0);
                    xf[kb][1] = *reinterpret_cast<const float2*>(xr1 + col0);
                    xf[kb][2] = *reinterpret_cast<const float2*>(xr0 + col0 + 8);
                    xf[kb][3] = *reinterpret_cast<const float2*>(xr1 + col0 + 8);
                }
                #pragma unroll
                for (int kb = 0; kb < 4; kb++) {
                    s[blk*2]   += fabsf(xf[kb][0].x) + fabsf(xf[kb][0].y) + fabsf(xf[kb][2].x) + fabsf(xf[kb][2].y);
                    s[blk*2+1] += fabsf(xf[kb][1].x) + fabsf(xf[kb][1].y) + fabsf(xf[kb][3].x) + fabsf(xf[kb][3].y);
                }
                #pragma unroll
                for (int kb = 0; kb < 4; kb++) {
                    u32 ah[4], al[4];
                    #pragma unroll
                    for (int j = 0; j < 4; j++) packhl(xf[kb][j].x, xf[kb][j].y, ah[j], al[j]);
                    #pragma unroll
                    for (int nbp = 0; nbp < 2; nbp++) {
                        mmabf(accA[blk][2*nbp],   ah, bh[kb][nbp][0], bh[kb][nbp][1]);
                        mmabf(accB[blk][2*nbp],   ah, bl[kb][nbp][0], bl[kb][nbp][1]);
                        mmabf(accB[blk][2*nbp],   al, bh[kb][nbp][0], bh[kb][nbp][1]);
                        mmabf(accA[blk][2*nbp+1], ah, bh[kb][nbp][2], bh[kb][nbp][3]);
                        mmabf(accB[blk][2*nbp+1], ah, bl[kb][nbp][2], bl[kb][nbp][3]);
                        mmabf(accB[blk][2*nbp+1], al, bh[kb][nbp][2], bh[kb][nbp][3]);
                    }
                }
            }
        }

        // ---- mask: quad-reduce per-row sum|x| ----
        #pragma unroll
        for (int i = 0; i < 4; i++) {
            s[i] += __shfl_xor_sync(0xffffffffu, s[i], 1);
            s[i] += __shfl_xor_sync(0xffffffffu, s[i], 2);
        }
        bool mr[4]; u32 bal[4];
        #pragma unroll
        for (int i = 0; i < 4; i++) {
            mr[i]  = s[i] > 128.0f;                  // sum>128 <=> mean|x|>1
            bal[i] = __ballot_sync(0xffffffffu, mr[i]);
        }

        // ---- epilogue1 in regs: bias+relu, re-split -> GEMM2 A-fragments ----
        u32 A2h[2][2][4], A2l[2][2][4];
        #pragma unroll
        for (int blk = 0; blk < 2; blk++)
            #pragma unroll
            for (int nb = 0; nb < 4; nb++) {
                float v0 = fmaxf(accA[blk][nb][0] + accB[blk][nb][0] + b2c[nb].x, 0.f);
                float v1 = fmaxf(accA[blk][nb][1] + accB[blk][nb][1] + b2c[nb].y, 0.f);
                float v2 = fmaxf(accA[blk][nb][2] + accB[blk][nb][2] + b2c[nb].x, 0.f);
                float v3 = fmaxf(accA[blk][nb][3] + accB[blk][nb][3] + b2c[nb].y, 0.f);
                const int kb2 = nb >> 1, base = (nb & 1) * 2;   // C layout == A layout
                packhl(v0, v1, A2h[blk][kb2][base + 0], A2l[blk][kb2][base + 0]);
                packhl(v2, v3, A2h[blk][kb2][base + 1], A2l[blk][kb2][base + 1]);
            }

        // ---- GEMM2: out = o2 @ Wf^T (M=32,N=128,K=32), B frags shared by 2 blocks ----
        #pragma unroll
        for (int nh = 0; nh < 2; nh++) {
            float acc2[2][8][4];
            #pragma unroll
            for (int blk = 0; blk < 2; blk++)
                #pragma unroll
                for (int nb = 0; nb < 8; nb++)
                    #pragma unroll
                    for (int j = 0; j < 4; j++) acc2[blk][nb][j] = 0.f;
            #pragma unroll
            for (int kb2 = 0; kb2 < 2; kb2++)
                #pragma unroll
                for (int nbp = 0; nbp < 4; nbp++) {
                    const u32 off = (u32)(((nh * 64 + nbp * 16) * ASTR + kb2 * 16) * 2);
                    u32 bh4[4], bl4[4];
                    ldmx4(bh4, wfh + off);
                    ldmx4(bl4, wfl + off);
                    #pragma unroll
                    for (int blk = 0; blk < 2; blk++) {
                        mmabf(acc2[blk][2*nbp],   A2h[blk][kb2], bh4[0], bh4[1]);
                        mmabf(acc2[blk][2*nbp],   A2h[blk][kb2], bl4[0], bl4[1]);
                        mmabf(acc2[blk][2*nbp],   A2l[blk][kb2], bh4[0], bh4[1]);
                        mmabf(acc2[blk][2*nbp+1], A2h[blk][kb2], bh4[2], bh4[3]);
                        mmabf(acc2[blk][2*nbp+1], A2h[blk][kb2], bl4[2], bl4[3]);
                        mmabf(acc2[blk][2*nbp+1], A2l[blk][kb2], bh4[2], bh4[3]);
                    }
                }
            #pragma unroll
            for (int blk = 0; blk < 2; blk++) {
                const long row1 = rw + blk * 16 + q, row2 = row1 + 8;
                #pragma unroll
                for (int nb = 0; nb < 8; nb++) {
                    const int col = nh * 64 + nb * 8 + c2;
                    const float2 bv = *reinterpret_cast<const float2*>(bfs + col);
                    if (!mr[blk*2])
                        *reinterpret_cast<float2*>(out + row1 * 128 + col) =
                            make_float2(acc2[blk][nb][0] + bv.x, acc2[blk][nb][1] + bv.y);
                    if (!mr[blk*2+1])
                        *reinterpret_cast<float2*>(out + row2 * 128 + col) =
                            make_float2(acc2[blk][nb][2] + bv.x, acc2[blk][nb][3] + bv.y);
                }
            }
        }

        // ---- rare slow path: masked rows computed fully in fp32 ----
        if (bal[0] | bal[1] | bal[2] | bal[3]) {
            float* o1s = scr + wid * 64;
            for (int r = 0; r < 32; r++) {
                if (!((bal[r >> 3] >> ((r & 7) * 4)) & 1u)) continue;
                const float4* xg4 = reinterpret_cast<const float4*>(X + (rw + r) * 128);
                #pragma unroll
                for (int uu = 0; uu < 2; uu++) {
                    const int u = lane + uu * 32;
                    const float4* wr = reinterpret_cast<const float4*>(W1 + u * 128);
                    float sacc = 0.f;
                    for (int k = 0; k < 32; k++) {
                        float4 a = xg4[k], w = wr[k];
                        sacc += a.x * w.x + a.y * w.y + a.z * w.z + a.w * w.w;
                    }
                    o1s[u] = fmaxf(sacc + b1[u], 0.f);
                }
                __syncwarp();
                #pragma unroll
                for (int jj = 0; jj < 4; jj++) {
                    const int d = lane + jj * 32;
                    const float* wf = Wf + d * 64;
                    float acc = bfs[d];
                    for (int u = 0; u < 64; u++) acc += o1s[u] * wf[u];
                    out[(rw + r) * 128 + d] = acc;
                }
                __syncwarp();
            }
        }
    }
}

extern "C" void kernel_launch(void* const* d_in, const int* in_sizes, int n_in,
                              void* d_out, int out_size)
{
    const float* X  = (const float*)d_in[0];
    const float* W1 = (const float*)d_in[1];
    const float* b1 = (const float*)d_in[2];
    const float* W2 = (const float*)d_in[3];
    const float* b2 = (const float*)d_in[4];
    const float* Wf = (const float*)d_in[5];
    const float* bf = (const float*)d_in[6];
    float* out = (float*)d_out;

    const int nrows = in_sizes[0] / 128;

    cudaFuncSetAttribute(dynlayer_mma,
                         cudaFuncAttributeMaxDynamicSharedMemorySize, SM_BYTES);
    int nsm = 148;
    cudaDeviceGetAttribute(&nsm, cudaDevAttrMultiProcessorCount, 0);

    dynlayer_mma<<<nsm, NTHREADS, SM_BYTES>>>(X, W1, b1, W2, b2, Wf, bf, out, nrows);
}